// round 8
// baseline (speedup 1.0000x reference)
#include <cuda_runtime.h>
#include <cuda_bf16.h>
#include <mma.h>

// Problem sizes (fixed by the dataset)
#define NN 65536
#define DD 32
#define HH 1024
#define CC 64

// Triangular staged-weight layout (see k_main):
//   sw2 region: sum_d L(d)      = 16399 float2  (L(d)=33d+1, L(0)=0)
//   sw1 region: sum_d (1024-L)  = 16369 float
#define SW2_F2   16399
#define SW1_F    16369
#define SW2_BYTES (SW2_F2 * 8)
#define SMEM_MAIN_BYTES (SW2_BYTES + SW1_F * 4)   // 196,668 B < 228 KB

// Degree-sorted unit layout:
//   deg(h) = h % 31 + 1; sorted prefix cum(g) = 33g+1 holds exactly units deg<=g
//   (deg 1 has 34 units, deg 2..31 have 33 each; cum(31)=1024).
// perm(j) = original unit index of sorted slot j.
__device__ __forceinline__ int perm_unit(int j) {
    int g, k;
    if (j < 34) { g = 1; k = j; }
    else        { g = (j - 1) / 33 + 1; k = j - (33 * (g - 1) + 1); }
    return (g - 1) + 31 * k;
}

// Fast, accurate-enough tanh: 1 - 2/(1+e^{2x}).
// ex2.approx rel err ~2^-22, rcp.approx ~2^-23 -> abs err ~1e-6.
// Saturation: x>>0 -> e=inf -> rcp=0 -> 1;  x<<0 -> e=0 -> 1-2 = -1.
__device__ __forceinline__ float tanh_fast(float v) {
    float e, r;
    asm("ex2.approx.f32 %0, %1;" : "=f"(e) : "f"(v * 2.885390081777927f)); // 2*log2(e)
    asm("rcp.approx.f32 %0, %1;" : "=f"(r) : "f"(e + 1.0f));
    return fmaf(-2.0f, r, 1.0f);
}

// Scratch (device globals: allocation-free per harness rules)
__device__ float  g_pre[(size_t)NN * HH];   // 256 MB: context@Wc + b1 (permuted cols)
__device__ float  g_W1p[DD * HH];           // W1p[d][j] = W1[d][perm(j)]
__device__ float2 g_W2p[DD * HH];           // W2p[d][j] = W2[perm(j)][d][0..1]
__device__ float  g_Wcp[CC * HH];           // Wcp[c][j] = Wc[c][perm(j)]
__device__ float  g_b1p[HH];

// ---------------------------------------------------------------------------
// Kernel 1: permute weights into degree-sorted order
// ---------------------------------------------------------------------------
__global__ void k_permute(const float* __restrict__ W1, const float* __restrict__ b1,
                          const float* __restrict__ Wc, const float* __restrict__ W2) {
    int j = blockIdx.x * blockDim.x + threadIdx.x;
    if (j >= HH) return;
    int h = perm_unit(j);
    g_b1p[j] = b1[h];
#pragma unroll
    for (int d = 0; d < DD; d++) g_W1p[d * HH + j] = W1[d * HH + h];
#pragma unroll
    for (int c = 0; c < CC; c++) g_Wcp[c * HH + j] = Wc[c * HH + h];
#pragma unroll
    for (int d = 0; d < DD; d++)
        g_W2p[d * HH + j] = make_float2(W2[h * (DD * 2) + d * 2 + 0],
                                        W2[h * (DD * 2) + d * 2 + 1]);
}

// ---------------------------------------------------------------------------
// Kernel 2: pre[n][j] = sum_c context[n][c] * Wcp[c][j] + b1p[j]
// tf32x3 wmma (m16n16k8), fp32 accumulate: A*B ~= AhBh + AlBh + AhBl.
// Each warp: 16 rows x 64 cols. Memory-bound on the 256 MB output write.
// ---------------------------------------------------------------------------
__global__ __launch_bounds__(128)
void k_pregemm(const float* __restrict__ ctx) {
    using namespace nvcuda;
    __shared__ float tile[4][16 * 64];   // per-warp epilogue staging (16 KB)

    int warpId = threadIdx.x >> 5;
    int lane   = threadIdx.x & 31;
    int gw = blockIdx.x * 4 + warpId;
    int ct = gw & 15;                    // col group: 64 cols
    int rt = gw >> 4;                    // row tile: 16 rows

    const float* Aptr = ctx + (size_t)rt * 16 * CC;

    wmma::fragment<wmma::accumulator, 16, 16, 8, float> acc[4];
#pragma unroll
    for (int c = 0; c < 4; c++) wmma::fill_fragment(acc[c], 0.0f);

#pragma unroll
    for (int k = 0; k < CC; k += 8) {
        wmma::fragment<wmma::matrix_a, 16, 16, 8, wmma::precision::tf32, wmma::row_major> aHi, aLo;
        wmma::load_matrix_sync(aHi, Aptr + k, CC);
#pragma unroll
        for (int t = 0; t < aHi.num_elements; t++) {
            float f  = aHi.x[t];
            float hi = wmma::__float_to_tf32(f);
            aHi.x[t] = hi;
            aLo.x[t] = wmma::__float_to_tf32(f - hi);
        }
#pragma unroll
        for (int c = 0; c < 4; c++) {
            wmma::fragment<wmma::matrix_b, 16, 16, 8, wmma::precision::tf32, wmma::row_major> bHi, bLo;
            wmma::load_matrix_sync(bHi, g_Wcp + k * HH + ct * 64 + c * 16, HH);
#pragma unroll
            for (int t = 0; t < bHi.num_elements; t++) {
                float f  = bHi.x[t];
                float hi = wmma::__float_to_tf32(f);
                bHi.x[t] = hi;
                bLo.x[t] = wmma::__float_to_tf32(f - hi);
            }
            wmma::mma_sync(acc[c], aHi, bHi, acc[c]);
            wmma::mma_sync(acc[c], aLo, bHi, acc[c]);
            wmma::mma_sync(acc[c], aHi, bLo, acc[c]);
        }
    }

    float* tw = &tile[warpId][0];
#pragma unroll
    for (int c = 0; c < 4; c++)
        wmma::store_matrix_sync(tw + c * 16, acc[c], 64, wmma::mem_row_major);
    __syncwarp();

    for (int i = lane; i < 16 * 64; i += 32) {
        int r = i >> 6, cc = i & 63;
        int col = ct * 64 + cc;
        g_pre[(size_t)(rt * 16 + r) * HH + col] = tw[r * 64 + cc] + g_b1p[col];
    }
}

// ---------------------------------------------------------------------------
// Kernel 3: sequential MADE sampling. One warp owns FOUR rows; state z[1024]
// per row lives in registers (thread holds units u = r*32+lane, r=0..31).
// The full triangular weight set (196.6 KB) is staged into shared ONCE at
// block entry, so the 32-step loop has NO barriers and no exposed weight
// latency. d-loop fully unrolled: per-step bounds and shared offsets are
// compile-time constants. 8 warps/block x 4 rows = 32 rows/block.
// ---------------------------------------------------------------------------
__global__ __launch_bounds__(256, 1)
void k_main(const float* __restrict__ x, const float* __restrict__ b2,
            float* __restrict__ out) {
    extern __shared__ char dynsmem[];
    float2* sm2 = (float2*)dynsmem;               // packed W2 prefixes
    float*  sm1 = (float*)(dynsmem + SW2_BYTES);  // packed W1 suffixes

    const int tid = threadIdx.x;
    const int lane = tid & 31;
    const int warpId = tid >> 5;

    // -------- stage the full triangular weight set (once) --------
    {
        int o1 = 0, o2 = 0;
#pragma unroll
        for (int d = 0; d < DD; d++) {
            const int L = d ? 33 * d + 1 : 0;
            for (int i = tid; i < L; i += 256)
                sm2[o2 + i] = g_W2p[d * HH + i];
            for (int i = tid; i < HH - L; i += 256)
                sm1[o1 + i] = g_W1p[d * HH + L + i];
            o2 += L; o1 += HH - L;
        }
    }

    // -------- per-warp row state --------
    const int nb = blockIdx.x * 32 + warpId * 4;   // 4 consecutive rows per warp
    float s[4][32];
    float xv[4], yacc[4], ld[4];
#pragma unroll
    for (int j = 0; j < 4; j++) {
        const float* p = g_pre + (size_t)(nb + j) * HH;
#pragma unroll
        for (int r = 0; r < 32; r++) s[j][r] = p[r * 32 + lane];
        xv[j] = x[(nb + j) * DD + lane];
        yacc[j] = 0.f; ld[j] = 0.f;
    }
    // b2 held lane-wise: lane d owns (shift_bias, logscale_bias) of dim d
    float b2s = b2[2 * lane + 0];
    float b2l = b2[2 * lane + 1];

    __syncthreads();   // staged weights visible; only barrier in the kernel

    int o1 = 0, o2 = 0;
#pragma unroll
    for (int d = 0; d < DD; d++) {
        const int L   = d ? 33 * d + 1 : 0;              // units with deg <= d (read set)
        const int fLo = (d >= 2) ? 33 * (d - 1) + 1 : 0; // freeze range [fLo, L): deg == d
        const float2* w2s = sm2 + o2;                    // w2s[u],   valid u in [0, L)
        const float*  w1s = sm1 + (o1 - L);              // w1s[u],   valid u in [L, 1024)

        float as[4] = {0.f, 0.f, 0.f, 0.f};
        float al[4] = {0.f, 0.f, 0.f, 0.f};
#pragma unroll
        for (int r = 0; r < 32; r++) {
            const int base = r * 32;
            const int u = base + lane;
            if (base < L && base + 32 > fLo) {     // slice intersects freeze range
                if (u >= fLo && u < L) {
#pragma unroll
                    for (int j = 0; j < 4; j++) s[j][r] = tanh_fast(s[j][r]);
                }
            }
            if (base < L) {                        // slice contributes to output d
                float2 w = w2s[u];
                if (u < L) {
#pragma unroll
                    for (int j = 0; j < 4; j++) {
                        as[j] = fmaf(s[j][r], w.x, as[j]);
                        al[j] = fmaf(s[j][r], w.y, al[j]);
                    }
                }
            }
        }
        // butterfly reduce across the warp (result on all lanes)
#pragma unroll
        for (int off = 16; off; off >>= 1) {
#pragma unroll
            for (int j = 0; j < 4; j++) {
                as[j] += __shfl_xor_sync(0xffffffffu, as[j], off);
                al[j] += __shfl_xor_sync(0xffffffffu, al[j], off);
            }
        }

        const float sb = __shfl_sync(0xffffffffu, b2s, d);
        const float lb = __shfl_sync(0xffffffffu, b2l, d);
        float yv[4];
#pragma unroll
        for (int j = 0; j < 4; j++) {
            float sh = as[j] + sb;
            float ls = al[j] + lb;
            float xd = __shfl_sync(0xffffffffu, xv[j], d);
            yv[j] = fmaf(xd, __expf(ls), sh);
            ld[j] += ls;
            if (lane == d) yacc[j] = yv[j];
        }

        // rank-1 update of the not-yet-frozen suffix (deg >= d+1)
#pragma unroll
        for (int r = 0; r < 32; r++) {
            const int base = r * 32;
            const int u = base + lane;
            if (base + 32 > L) {
                float w = w1s[u];
                if (u >= L) {
#pragma unroll
                    for (int j = 0; j < 4; j++) s[j][r] = fmaf(yv[j], w, s[j][r]);
                }
            }
        }
        o2 += L; o1 += HH - L;
    }

    // outputs: y [N,D] then log_det [N]
#pragma unroll
    for (int j = 0; j < 4; j++) {
        out[(size_t)(nb + j) * DD + lane] = yacc[j];
        if (lane == 0) out[(size_t)NN * DD + (nb + j)] = ld[j];
    }
}

// ---------------------------------------------------------------------------
extern "C" void kernel_launch(void* const* d_in, const int* in_sizes, int n_in,
                              void* d_out, int out_size) {
    const float* x   = (const float*)d_in[0];
    const float* ctx = (const float*)d_in[1];
    const float* W1  = (const float*)d_in[2];
    const float* b1  = (const float*)d_in[3];
    const float* Wc  = (const float*)d_in[4];
    const float* W2  = (const float*)d_in[5];
    const float* b2  = (const float*)d_in[6];
    float* out = (float*)d_out;

    // Opt-in to >48KB dynamic shared memory (host-side attribute set, not an
    // allocation; idempotent and capture-safe).
    static int smem_set = 0;
    if (!smem_set) {
        cudaFuncSetAttribute(k_main, cudaFuncAttributeMaxDynamicSharedMemorySize,
                             SMEM_MAIN_BYTES);
        smem_set = 1;
    }

    k_permute<<<(HH + 127) / 128, 128>>>(W1, b1, Wc, W2);
    k_pregemm<<<(NN / 16) * (HH / 64) / 4, 128>>>(ctx);   // 16384 blocks x 4 warps
    k_main<<<NN / 32, 256, SMEM_MAIN_BYTES>>>(x, b2, out);
}

// round 11
// speedup vs baseline: 2.9006x; 2.9006x over previous
#include <cuda_runtime.h>
#include <cuda_bf16.h>
#include <mma.h>

// Problem sizes (fixed by the dataset)
#define NN 65536
#define DD 32
#define HH 1024
#define CC 64

// Triangular staged-weight layout (see k_main):
//   sw2 region: sum_d L(d)      = 16399 float2  (L(d)=33d+1, L(0)=0)
//   sw1 region: sum_d (1024-L)  = 16369 float
#define SW2_F2   16399
#define SW1_F    16369
#define SW2_BYTES (SW2_F2 * 8)
#define SMEM_MAIN_BYTES (SW2_BYTES + SW1_F * 4)   // 196,668 B < 228 KB

// Degree-sorted unit layout:
//   deg(h) = h % 31 + 1; sorted prefix cum(g) = 33g+1 holds exactly units deg<=g
//   (deg 1 has 34 units, deg 2..31 have 33 each; cum(31)=1024).
// perm(j) = original unit index of sorted slot j.
__device__ __forceinline__ int perm_unit(int j) {
    int g, k;
    if (j < 34) { g = 1; k = j; }
    else        { g = (j - 1) / 33 + 1; k = j - (33 * (g - 1) + 1); }
    return (g - 1) + 31 * k;
}

// Fast, accurate-enough tanh: 1 - 2/(1+e^{2x}).
// ex2.approx rel err ~2^-22, rcp.approx ~2^-23 -> abs err ~1e-6; saturates
// correctly at +/-inf.
__device__ __forceinline__ float tanh_fast(float v) {
    float e, r;
    asm("ex2.approx.f32 %0, %1;" : "=f"(e) : "f"(v * 2.885390081777927f)); // 2*log2(e)
    asm("rcp.approx.f32 %0, %1;" : "=f"(r) : "f"(e + 1.0f));
    return fmaf(-2.0f, r, 1.0f);
}

// Scratch (device globals: allocation-free per harness rules)
__device__ float  g_pre[(size_t)NN * HH];   // 256 MB: context@Wc + b1 (permuted cols)
__device__ float  g_W1p[DD * HH];           // W1p[d][j] = W1[d][perm(j)]
__device__ float2 g_W2p[DD * HH];           // W2p[d][j] = W2[perm(j)][d][0..1]
__device__ float  g_Wcp[CC * HH];           // Wcp[c][j] = Wc[c][perm(j)]
__device__ float  g_b1p[HH];

// ---------------------------------------------------------------------------
// Kernel 1: permute weights into degree-sorted order
// ---------------------------------------------------------------------------
__global__ void k_permute(const float* __restrict__ W1, const float* __restrict__ b1,
                          const float* __restrict__ Wc, const float* __restrict__ W2) {
    int j = blockIdx.x * blockDim.x + threadIdx.x;
    if (j >= HH) return;
    int h = perm_unit(j);
    g_b1p[j] = b1[h];
#pragma unroll
    for (int d = 0; d < DD; d++) g_W1p[d * HH + j] = W1[d * HH + h];
#pragma unroll
    for (int c = 0; c < CC; c++) g_Wcp[c * HH + j] = Wc[c * HH + h];
#pragma unroll
    for (int d = 0; d < DD; d++)
        g_W2p[d * HH + j] = make_float2(W2[h * (DD * 2) + d * 2 + 0],
                                        W2[h * (DD * 2) + d * 2 + 1]);
}

// ---------------------------------------------------------------------------
// Kernel 2: pre[n][j] = sum_c context[n][c] * Wcp[c][j] + b1p[j]
// tf32x3 wmma (m16n16k8), fp32 accumulate: A*B ~= AhBh + AlBh + AhBl.
// Each warp: 16 rows x 64 cols. Memory-bound on the 256 MB output write.
// ---------------------------------------------------------------------------
__global__ __launch_bounds__(128)
void k_pregemm(const float* __restrict__ ctx) {
    using namespace nvcuda;
    __shared__ float tile[4][16 * 64];

    int warpId = threadIdx.x >> 5;
    int lane   = threadIdx.x & 31;
    int gw = blockIdx.x * 4 + warpId;
    int ct = gw & 15;
    int rt = gw >> 4;

    const float* Aptr = ctx + (size_t)rt * 16 * CC;

    wmma::fragment<wmma::accumulator, 16, 16, 8, float> acc[4];
#pragma unroll
    for (int c = 0; c < 4; c++) wmma::fill_fragment(acc[c], 0.0f);

#pragma unroll
    for (int k = 0; k < CC; k += 8) {
        wmma::fragment<wmma::matrix_a, 16, 16, 8, wmma::precision::tf32, wmma::row_major> aHi, aLo;
        wmma::load_matrix_sync(aHi, Aptr + k, CC);
#pragma unroll
        for (int t = 0; t < aHi.num_elements; t++) {
            float f  = aHi.x[t];
            float hi = wmma::__float_to_tf32(f);
            aHi.x[t] = hi;
            aLo.x[t] = wmma::__float_to_tf32(f - hi);
        }
#pragma unroll
        for (int c = 0; c < 4; c++) {
            wmma::fragment<wmma::matrix_b, 16, 16, 8, wmma::precision::tf32, wmma::row_major> bHi, bLo;
            wmma::load_matrix_sync(bHi, g_Wcp + k * HH + ct * 64 + c * 16, HH);
#pragma unroll
            for (int t = 0; t < bHi.num_elements; t++) {
                float f  = bHi.x[t];
                float hi = wmma::__float_to_tf32(f);
                bHi.x[t] = hi;
                bLo.x[t] = wmma::__float_to_tf32(f - hi);
            }
            wmma::mma_sync(acc[c], aHi, bHi, acc[c]);
            wmma::mma_sync(acc[c], aLo, bHi, acc[c]);
            wmma::mma_sync(acc[c], aHi, bLo, acc[c]);
        }
    }

    float* tw = &tile[warpId][0];
#pragma unroll
    for (int c = 0; c < 4; c++)
        wmma::store_matrix_sync(tw + c * 16, acc[c], 64, wmma::mem_row_major);
    __syncwarp();

    for (int i = lane; i < 16 * 64; i += 32) {
        int r = i >> 6, cc = i & 63;
        int col = ct * 64 + cc;
        g_pre[(size_t)(rt * 16 + r) * HH + col] = tw[r * 64 + cc] + g_b1p[col];
    }
}

// ---------------------------------------------------------------------------
// Kernel 3: sequential MADE sampling. One warp owns FOUR rows; state z[1024]
// per row in registers (thread holds units u = r*32+lane, r=0..31).
// Structure: 4 UNROLLED groups x 8 ROLLED d-steps. Within group g the r-loop
// bounds are STATIC (read r < 8(g+1), update r >= 8g), so s[][] indexing is
// compile-time -> guaranteed register residency, small code (~4 step bodies).
// Runtime L predicates handle the exact triangular boundary inside a group.
// Full triangular weight set staged into shared ONCE; no barriers in the loop.
// ---------------------------------------------------------------------------
__global__ __launch_bounds__(256, 1)
void k_main(const float* __restrict__ x, const float* __restrict__ b2,
            float* __restrict__ out) {
    extern __shared__ char dynsmem[];
    float2* sm2 = (float2*)dynsmem;               // packed W2 prefixes
    float*  sm1 = (float*)(dynsmem + SW2_BYTES);  // packed W1 suffixes

    const int tid = threadIdx.x;
    const int lane = tid & 31;
    const int warpId = tid >> 5;

    // -------- stage the full triangular weight set (once, rolled/compact) ----
    {
        int o1 = 0, o2 = 0;
        for (int d = 0; d < DD; d++) {
            const int L = d ? 33 * d + 1 : 0;
            for (int i = tid; i < L; i += 256)      sm2[o2 + i] = g_W2p[d * HH + i];
            for (int i = tid; i < HH - L; i += 256) sm1[o1 + i] = g_W1p[d * HH + L + i];
            o2 += L; o1 += HH - L;
        }
    }

    // -------- per-warp row state --------
    const int nb = blockIdx.x * 32 + warpId * 4;   // 4 consecutive rows per warp
    float s[4][32];
    float xv[4], yacc[4], ld[4];
#pragma unroll
    for (int j = 0; j < 4; j++) {
        const float* p = g_pre + (size_t)(nb + j) * HH;
#pragma unroll
        for (int r = 0; r < 32; r++) s[j][r] = p[r * 32 + lane];
        xv[j] = x[(nb + j) * DD + lane];
        yacc[j] = 0.f; ld[j] = 0.f;
    }
    // b2 held lane-wise: lane d owns (shift_bias, logscale_bias) of dim d
    float b2s = b2[2 * lane + 0];
    float b2l = b2[2 * lane + 1];

    __syncthreads();   // staged weights visible; only barrier in the kernel

    int o1 = 0, o2 = 0;
#pragma unroll
    for (int grp = 0; grp < 4; grp++) {
        const int R_RD = 8 * (grp + 1);   // static: read slices r in [0, R_RD)
        const int R_UP = 8 * grp;         // static: update slices r in [R_UP, 32)

#pragma unroll 1
        for (int dd = 0; dd < 8; dd++) {
            const int d   = grp * 8 + dd;
            const int L   = d ? 33 * d + 1 : 0;              // read set [0, L)
            const int fLo = (d >= 2) ? 33 * (d - 1) + 1 : 0; // freeze [fLo, L)
            const float2* w2s = sm2 + o2;                    // valid u in [0, L)
            const float*  w1s = sm1 + (o1 - L);              // valid u in [L, 1024)

            float as[4] = {0.f, 0.f, 0.f, 0.f};
            float al[4] = {0.f, 0.f, 0.f, 0.f};
#pragma unroll
            for (int r = 0; r < R_RD; r++) {
                const int base = r * 32;
                const int u = base + lane;
                if (base < L) {
                    if (u >= fLo && u < L) {
#pragma unroll
                        for (int j = 0; j < 4; j++) s[j][r] = tanh_fast(s[j][r]);
                    }
                    if (u < L) {
                        float2 w = w2s[u];
#pragma unroll
                        for (int j = 0; j < 4; j++) {
                            as[j] = fmaf(s[j][r], w.x, as[j]);
                            al[j] = fmaf(s[j][r], w.y, al[j]);
                        }
                    }
                }
            }
            // butterfly reduce across the warp (result on all lanes)
#pragma unroll
            for (int off = 16; off; off >>= 1) {
#pragma unroll
                for (int j = 0; j < 4; j++) {
                    as[j] += __shfl_xor_sync(0xffffffffu, as[j], off);
                    al[j] += __shfl_xor_sync(0xffffffffu, al[j], off);
                }
            }

            const float sb = __shfl_sync(0xffffffffu, b2s, d);
            const float lb = __shfl_sync(0xffffffffu, b2l, d);
            float yv[4];
#pragma unroll
            for (int j = 0; j < 4; j++) {
                float sh = as[j] + sb;
                float ls = al[j] + lb;
                float xd = __shfl_sync(0xffffffffu, xv[j], d);
                yv[j] = fmaf(xd, __expf(ls), sh);
                ld[j] += ls;
                if (lane == d) yacc[j] = yv[j];
            }

            // rank-1 update of the not-yet-frozen suffix (deg >= d+1)
#pragma unroll
            for (int r = R_UP; r < 32; r++) {
                const int base = r * 32;
                const int u = base + lane;
                if (base + 32 > L) {
                    if (u >= L) {
                        float w = w1s[u];
#pragma unroll
                        for (int j = 0; j < 4; j++) s[j][r] = fmaf(yv[j], w, s[j][r]);
                    }
                }
            }
            o2 += L; o1 += HH - L;
        }
    }

    // outputs: y [N,D] then log_det [N]
#pragma unroll
    for (int j = 0; j < 4; j++) {
        out[(size_t)(nb + j) * DD + lane] = yacc[j];
        if (lane == 0) out[(size_t)NN * DD + (nb + j)] = ld[j];
    }
}

// ---------------------------------------------------------------------------
extern "C" void kernel_launch(void* const* d_in, const int* in_sizes, int n_in,
                              void* d_out, int out_size) {
    const float* x   = (const float*)d_in[0];
    const float* ctx = (const float*)d_in[1];
    const float* W1  = (const float*)d_in[2];
    const float* b1  = (const float*)d_in[3];
    const float* Wc  = (const float*)d_in[4];
    const float* W2  = (const float*)d_in[5];
    const float* b2  = (const float*)d_in[6];
    float* out = (float*)d_out;

    // Host-side attribute set (not an allocation; idempotent, capture-safe).
    static int smem_set = 0;
    if (!smem_set) {
        cudaFuncSetAttribute(k_main, cudaFuncAttributeMaxDynamicSharedMemorySize,
                             SMEM_MAIN_BYTES);
        smem_set = 1;
    }

    k_permute<<<(HH + 127) / 128, 128>>>(W1, b1, Wc, W2);
    k_pregemm<<<(NN / 16) * (HH / 64) / 4, 128>>>(ctx);   // 16384 blocks x 4 warps
    k_main<<<NN / 32, 256, SMEM_MAIN_BYTES>>>(x, b2, out);
}